// round 9
// baseline (speedup 1.0000x reference)
#include <cuda_runtime.h>
#include <cstdint>

// Problem constants (fixed-shape problem)
#define BB 4
#define TT 12
#define NN 10000
#define FF 32
#define EE 160000
#define MM (BB*NN)          // 40000 rows
#define SLICES (BB*TT)      // 48
#define SL (NN*FF)          // 320000 elements per slice
#define SL2 (SL/2)          // slice stride in float2/ull units
#define NTG 6               // timestep-groups (2 steps each)

typedef unsigned long long ull;

// -------- device scratch (static, no allocation; zero-initialized at load) ----
__device__ float d_XA[SLICES * NN * FF];   // aggregated features (61.4MB)
__device__ float d_deg[NN];
__device__ float d_dinv[NN];
__device__ int   d_cnt[NN];
__device__ int   d_fill[NN];
__device__ int   d_rowptr[NN + 1];
__device__ int2  d_csrp[EE];               // packed {src_row, weight_bits}
__device__ float d_Wpack[32 * 32 * 4];     // [k][j][{Wz',Wr',Wh',Uz}]
__device__ float d_Ur[1024];
__device__ float d_Uh[1024];
__device__ float d_bf[96];                 // folded biases z|r|h
__device__ float d_probs[TT];
__device__ int   d_done[8];                // per-tg completion counters (NTG used)

// ===================== helpers =====================
__device__ __forceinline__ void fma2(ull& d, ull a, ull b) {
    asm("fma.rn.f32x2 %0, %1, %2, %0;" : "+l"(d) : "l"(a), "l"(b));
}
__device__ __forceinline__ void mul2(ull& d, ull a, ull b) {
    asm("mul.rn.f32x2 %0, %1, %2;" : "=l"(d) : "l"(a), "l"(b));
}
__device__ __forceinline__ ull splat2(float w) {
    ull r; asm("mov.b64 %0, {%1, %1};" : "=l"(r) : "f"(w)); return r;
}
__device__ __forceinline__ float2 unpk(ull a) {
    float2 f; asm("mov.b64 {%0, %1}, %2;" : "=f"(f.x), "=f"(f.y) : "l"(a)); return f;
}
__device__ __forceinline__ int ld_acq(const int* p) {
    int v;
    asm volatile("ld.acquire.gpu.global.b32 %0, [%1];" : "=r"(v) : "l"(p) : "memory");
    return v;
}

// -------- degree/count accumulation --------
__global__ void k_degcnt(const int* ei, const float* ew) {
    int e = blockIdx.x * blockDim.x + threadIdx.x;
    if (e >= EE) return;
    int col = ei[EE + e];
    atomicAdd(&d_deg[col], ew[e]);
    atomicAdd(&d_cnt[col], 1);
}

// fused single-block kernel: dinv + 3-level exclusive scan (cnt -> rowptr)
// + weight folding + attention softmax + counter/flag re-zero.
__global__ void k_scan_prep(const float* att,
                            const float* Wz, const float* bz, const float* lzw, const float* lzb,
                            const float* Wr, const float* br, const float* lrw, const float* lrb,
                            const float* Wh, const float* bh, const float* lhw, const float* lhb) {
    int tid = threadIdx.x;
    int lane = tid & 31;

    // ---- weight folding ----
    {
        const float* Ws[3]  = {Wz, Wr, Wh};
        const float* bs[3]  = {bz, br, bh};
        const float* ls[3]  = {lzw, lrw, lhw};
        const float* lbs[3] = {lzb, lrb, lhb};
        int k = tid >> 5, j = tid & 31;
        #pragma unroll
        for (int g = 0; g < 3; g++) {
            float s = 0.f;
            #pragma unroll
            for (int m = 0; m < 32; m++) s += Ws[g][k * 32 + m] * ls[g][m * 32 + j];
            d_Wpack[(k * 32 + j) * 4 + g] = s;
        }
        d_Wpack[(k * 32 + j) * 4 + 3] = lzw[(32 + k) * 32 + j];  // Uz
        d_Ur[k * 32 + j] = lrw[(32 + k) * 32 + j];
        d_Uh[k * 32 + j] = lhw[(32 + k) * 32 + j];
        if (tid < 96) {
            int g = tid >> 5; int jj = tid & 31;
            float s = lbs[g][jj];
            for (int m = 0; m < 32; m++) s += bs[g][m] * ls[g][m * 32 + jj];
            d_bf[g * 32 + jj] = s;
        }
        if (tid == 0) {
            float mx = -1e30f;
            for (int i = 0; i < TT; i++) mx = fmaxf(mx, att[i]);
            float e[TT]; float sum = 0.f;
            for (int i = 0; i < TT; i++) { e[i] = expf(att[i] - mx); sum += e[i]; }
            for (int i = 0; i < TT; i++) d_probs[i] = e[i] / sum;
        }
    }

    // ---- dinv ----
    for (int i = tid; i < NN; i += 1024) {
        float d = d_deg[i] + 1.0f;
        d_dinv[i] = rsqrtf(fmaxf(d, 1e-12f));
    }

    // ---- 3-level exclusive scan ----
    __shared__ int warpsum[32];
    int v[10];
    int s = 0;
    int base = tid * 10;
    if (tid < 1000) {
        #pragma unroll
        for (int u = 0; u < 10; u++) { v[u] = s; s += d_cnt[base + u]; }
    }
    int inc = s;
    #pragma unroll
    for (int o = 1; o < 32; o <<= 1) {
        int t = __shfl_up_sync(0xffffffffu, inc, o);
        if (lane >= o) inc += t;
    }
    if (lane == 31) warpsum[tid >> 5] = inc;
    __syncthreads();
    if (tid < 32) {
        int ws = warpsum[tid];
        int winc = ws;
        #pragma unroll
        for (int o = 1; o < 32; o <<= 1) {
            int t = __shfl_up_sync(0xffffffffu, winc, o);
            if (lane >= o) winc += t;
        }
        warpsum[tid] = winc - ws;
    }
    __syncthreads();
    int texcl = warpsum[tid >> 5] + inc - s;
    if (tid < 1000) {
        #pragma unroll
        for (int u = 0; u < 10; u++) d_rowptr[base + u] = texcl + v[u];
    }
    if (tid == 1000) d_rowptr[NN] = texcl;

    // ---- re-zero counters + producer/consumer flags ----
    __syncthreads();
    for (int i = tid; i < NN; i += 1024) { d_deg[i] = 0.f; d_cnt[i] = 0; d_fill[i] = 0; }
    if (tid < 8) d_done[tid] = 0;
}

__global__ void k_fill(const int* ei, const float* ew) {
    int e = blockIdx.x * blockDim.x + threadIdx.x;
    if (e >= EE) return;
    int r = ei[e];
    int c = ei[EE + e];
    int pos = d_rowptr[c] + atomicAdd(&d_fill[c], 1);
    float w = d_dinv[r] * ew[e] * d_dinv[c];
    d_csrp[pos] = make_int2(r, __float_as_int(w));
}

// ==================== FUSED agg ∥ gru kernel ====================
// Grid sized to exactly one co-resident wave (host queries occupancy), so
// producer (agg) and consumer (gru) blocks are all scheduled simultaneously
// => no starvation/deadlock. agg role: grid-stride over 60000 (tg,node)
// tasks in t-major order, release-counting into d_done[tg]. gru role:
// grid-stride over 1250 row-groups, acquire-polling d_done before each
// timestep-group, reading XA via ld.global.cg (L2-coherent).
__global__ void __launch_bounds__(128)
k_fused(const float* __restrict__ x,
        const float* __restrict__ linw, const float* __restrict__ linb,
        float* __restrict__ out, int aggB, int nblk) {
    __shared__ float sW4[4096];            // [k*32+j][4] = {Wz',Wr',Wh',Uz}
    __shared__ float sUr[1024], sUh[1024];
    __shared__ float sb[96];
    __shared__ float sprob[16];
    __shared__ __align__(16) float stg[4][3][256];   // per-warp xaT | hT | hrT

    int tid = threadIdx.x;
    int w = tid >> 5, lane = tid & 31;

    if ((int)blockIdx.x < aggB) {
        // ---------------- agg role ----------------
        int half = lane >> 4;              // t-parity within the tg
        int fp = lane & 15;                // feature-pair index
        const ull* px = (const ull*)x;
        int stride = aggB * 4;
        for (int task = blockIdx.x * 4 + w; task < NN * NTG; task += stride) {
            int tg = task / NN;
            int n = task - tg * NN;
            int t = 2 * tg + half;
            // accumulator p <-> batch b=p; slice (b,t) at (b*TT+t)*SL
            long o0 = (long)(0 * TT + t) * SL2 + fp;
            long o1 = (long)(1 * TT + t) * SL2 + fp;
            long o2 = (long)(2 * TT + t) * SL2 + fp;
            long o3 = (long)(3 * TT + t) * SL2 + fp;

            float dn = d_dinv[n];
            ull selfw2 = splat2(dn * dn);
            ull acc0, acc1, acc2, acc3;
            {
                int r16 = n * 16;
                mul2(acc0, __ldg(px + o0 + r16), selfw2);
                mul2(acc1, __ldg(px + o1 + r16), selfw2);
                mul2(acc2, __ldg(px + o2 + r16), selfw2);
                mul2(acc3, __ldg(px + o3 + r16), selfw2);
            }
            int e0 = d_rowptr[n], e1 = d_rowptr[n + 1];
            int2 ed;
            if (e0 < e1) ed = __ldg(&d_csrp[e0]);
            for (int e = e0; e < e1; e++) {
                int2 edn;
                if (e + 1 < e1) edn = __ldg(&d_csrp[e + 1]);
                ull w2 = splat2(__int_as_float(ed.y));
                int r16 = ed.x * 16;
                ull v0 = __ldg(px + o0 + r16);
                ull v1 = __ldg(px + o1 + r16);
                ull v2 = __ldg(px + o2 + r16);
                ull v3 = __ldg(px + o3 + r16);
                fma2(acc0, v0, w2);
                fma2(acc1, v1, w2);
                fma2(acc2, v2, w2);
                fma2(acc3, v3, w2);
                ed = edn;
            }
            float2* po = (float2*)d_XA;
            int n16 = n * 16 + fp;
            __stcs(po + (long)(0 * TT + t) * SL2 + n16, unpk(acc0));
            __stcs(po + (long)(1 * TT + t) * SL2 + n16, unpk(acc1));
            __stcs(po + (long)(2 * TT + t) * SL2 + n16, unpk(acc2));
            __stcs(po + (long)(3 * TT + t) * SL2 + n16, unpk(acc3));

            __threadfence();               // release all lanes' stores
            __syncwarp();
            if (lane == 0) atomicAdd(&d_done[tg], 1);
        }
        return;
    }

    // ---------------- gru role ----------------
    for (int i = tid; i < 4096; i += 128) sW4[i] = d_Wpack[i];
    for (int i = tid; i < 1024; i += 128) {
        sUr[i] = d_Ur[i]; sUh[i] = d_Uh[i];
    }
    if (tid < 96) sb[tid] = d_bf[tid];
    if (tid < TT) sprob[tid] = d_probs[tid];
    __syncthreads();

    int gid = blockIdx.x - aggB;
    int G = nblk - aggB;
    float* xaT = stg[w][0];
    float* hT  = stg[w][1];
    float* hrT = stg[w][2];
    int j = lane;
    ull bz2 = splat2(sb[j]), br2 = splat2(sb[32 + j]), bh2 = splat2(sb[64 + j]);
    int tgok = -1;                          // highest tg confirmed complete

    for (int rb = gid; rb < MM / 32; rb += G) {
        int m0 = rb * 32 + w * 8;
        // NN % 8 == 0 => a warp's 8 rows stay within one batch
        int b = m0 / NN;
        int base = b * (TT * SL) + (m0 - b * NN) * 32 + j;

        float h[8], hacc[8];
        #pragma unroll
        for (int r = 0; r < 8; r++) { h[r] = 0.f; hacc[r] = 0.f; }

        for (int t = 0; t < TT; t++) {
            int tgn = t >> 1;
            if (tgn > tgok) {              // acquire-poll producer progress
                while (ld_acq(&d_done[tgn]) < NN) __nanosleep(128);
                tgok = tgn;
            }
            float xa[8];
            #pragma unroll
            for (int r = 0; r < 8; r++)
                xa[r] = __ldcg(&d_XA[base + t * SL + r * 32]);  // L2-coherent

            __syncwarp();
            ((float4*)(xaT + j * 8))[0] = make_float4(xa[0], xa[1], xa[2], xa[3]);
            ((float4*)(xaT + j * 8))[1] = make_float4(xa[4], xa[5], xa[6], xa[7]);
            ((float4*)(hT  + j * 8))[0] = make_float4(h[0], h[1], h[2], h[3]);
            ((float4*)(hT  + j * 8))[1] = make_float4(h[4], h[5], h[6], h[7]);
            __syncwarp();

            ull az[4], ar[4], ah[4];
            #pragma unroll
            for (int p = 0; p < 4; p++) { az[p] = bz2; ar[p] = br2; ah[p] = bh2; }

            #pragma unroll 4
            for (int k = 0; k < 32; k++) {
                ulonglong2 x01 = ((const ulonglong2*)(xaT + k * 8))[0];
                ulonglong2 x23 = ((const ulonglong2*)(xaT + k * 8))[1];
                ulonglong2 h01 = ((const ulonglong2*)(hT  + k * 8))[0];
                ulonglong2 h23 = ((const ulonglong2*)(hT  + k * 8))[1];
                float4 w4 = ((const float4*)sW4)[k * 32 + j];
                float urv = sUr[k * 32 + j];
                ull wz2 = splat2(w4.x), wr2 = splat2(w4.y), wh2 = splat2(w4.z);
                ull uz2 = splat2(w4.w), ur2 = splat2(urv);
                ull xp[4] = {x01.x, x01.y, x23.x, x23.y};
                ull hp[4] = {h01.x, h01.y, h23.x, h23.y};
                #pragma unroll
                for (int p = 0; p < 4; p++) {
                    fma2(az[p], xp[p], wz2); fma2(az[p], hp[p], uz2);
                    fma2(ar[p], xp[p], wr2); fma2(ar[p], hp[p], ur2);
                    fma2(ah[p], xp[p], wh2);
                }
            }

            float z[8], hr[8];
            #pragma unroll
            for (int p = 0; p < 4; p++) {
                float2 a = unpk(az[p]);
                float2 b2 = unpk(ar[p]);
                z[2 * p]     = 1.f / (1.f + __expf(-a.x));
                z[2 * p + 1] = 1.f / (1.f + __expf(-a.y));
                hr[2 * p]     = h[2 * p]     * (1.f / (1.f + __expf(-b2.x)));
                hr[2 * p + 1] = h[2 * p + 1] * (1.f / (1.f + __expf(-b2.y)));
            }
            __syncwarp();
            ((float4*)(hrT + j * 8))[0] = make_float4(hr[0], hr[1], hr[2], hr[3]);
            ((float4*)(hrT + j * 8))[1] = make_float4(hr[4], hr[5], hr[6], hr[7]);
            __syncwarp();

            #pragma unroll 4
            for (int k = 0; k < 32; k++) {
                ulonglong2 r01 = ((const ulonglong2*)(hrT + k * 8))[0];
                ulonglong2 r23 = ((const ulonglong2*)(hrT + k * 8))[1];
                ull uh2 = splat2(sUh[k * 32 + j]);
                fma2(ah[0], r01.x, uh2); fma2(ah[1], r01.y, uh2);
                fma2(ah[2], r23.x, uh2); fma2(ah[3], r23.y, uh2);
            }

            float pt = sprob[t];
            #pragma unroll
            for (int p = 0; p < 4; p++) {
                float2 a = unpk(ah[p]);
                float ht0 = 2.f / (1.f + __expf(-2.f * a.x)) - 1.f;   // tanh
                float ht1 = 2.f / (1.f + __expf(-2.f * a.y)) - 1.f;
                int r0 = 2 * p, r1 = 2 * p + 1;
                h[r0] = z[r0] * h[r0] + (1.f - z[r0]) * ht0;
                h[r1] = z[r1] * h[r1] + (1.f - z[r1]) * ht1;
                hacc[r0] += pt * h[r0];
                hacc[r1] += pt * h[r1];
            }
        }

        // final: out = relu(Hacc) @ lin_w + lin_b   (lin_w via L2)
        __syncwarp();
        ((float4*)(xaT + j * 8))[0] = make_float4(fmaxf(hacc[0], 0.f), fmaxf(hacc[1], 0.f),
                                                  fmaxf(hacc[2], 0.f), fmaxf(hacc[3], 0.f));
        ((float4*)(xaT + j * 8))[1] = make_float4(fmaxf(hacc[4], 0.f), fmaxf(hacc[5], 0.f),
                                                  fmaxf(hacc[6], 0.f), fmaxf(hacc[7], 0.f));
        __syncwarp();

        ull lb2 = splat2(__ldg(&linb[j]));
        ull acc[4] = {lb2, lb2, lb2, lb2};
        #pragma unroll 4
        for (int k = 0; k < 32; k++) {
            ulonglong2 v01 = ((const ulonglong2*)(xaT + k * 8))[0];
            ulonglong2 v23 = ((const ulonglong2*)(xaT + k * 8))[1];
            ull lw2 = splat2(__ldg(&linw[k * 32 + j]));
            fma2(acc[0], v01.x, lw2); fma2(acc[1], v01.y, lw2);
            fma2(acc[2], v23.x, lw2); fma2(acc[3], v23.y, lw2);
        }
        #pragma unroll
        for (int p = 0; p < 4; p++) {
            float2 a = unpk(acc[p]);
            out[(m0 + 2 * p) * 32 + j] = a.x;
            out[(m0 + 2 * p + 1) * 32 + j] = a.y;
        }
        __syncwarp();
    }
}

extern "C" void kernel_launch(void* const* d_in, const int* in_sizes, int n_in,
                              void* d_out, int out_size) {
    const float* x  = (const float*)d_in[0];
    const int*   ei = (const int*)d_in[1];
    const float* ew = (const float*)d_in[2];

    // Detect weight ordering (dict vs signature) via in_sizes[5]
    int iWz, iBz, iLzw, iLzb, iWr, iBr, iLrw, iLrb, iWh, iBh, iLhw, iLhb;
    if (in_sizes[5] == 2048) {
        iWz = 3; iBz = 4; iLzw = 5;  iLzb = 6;
        iWr = 7; iBr = 8; iLrw = 9;  iLrb = 10;
        iWh = 11; iBh = 12; iLhw = 13; iLhb = 14;
    } else {
        iWz = 3; iBz = 4; iWr = 5; iBr = 6; iWh = 7; iBh = 8;
        iLzw = 9; iLzb = 10; iLrw = 11; iLrb = 12; iLhw = 13; iLhb = 14;
    }
    const float* Wz  = (const float*)d_in[iWz];
    const float* bz  = (const float*)d_in[iBz];
    const float* lzw = (const float*)d_in[iLzw];
    const float* lzb = (const float*)d_in[iLzb];
    const float* Wr  = (const float*)d_in[iWr];
    const float* br  = (const float*)d_in[iBr];
    const float* lrw = (const float*)d_in[iLrw];
    const float* lrb = (const float*)d_in[iLrb];
    const float* Wh  = (const float*)d_in[iWh];
    const float* bh  = (const float*)d_in[iBh];
    const float* lhw = (const float*)d_in[iLhw];
    const float* lhb = (const float*)d_in[iLhb];
    const float* att  = (const float*)d_in[15];
    const float* linw = (const float*)d_in[16];
    const float* linb = (const float*)d_in[17];
    float* out = (float*)d_out;

    // Size the fused grid to exactly one co-resident wave (deadlock-free by
    // construction). Host-side queries: capture-legal, deterministic.
    static int nblk = 0, aggB = 0;
    if (nblk == 0) {
        int nsm = 148, occ = 4;
        cudaDeviceGetAttribute(&nsm, cudaDevAttrMultiProcessorCount, 0);
        cudaOccupancyMaxActiveBlocksPerMultiprocessor(&occ, k_fused, 128, 0);
        if (nsm <= 0) nsm = 148;
        if (occ <= 0) occ = 1;
        nblk = nsm * occ;
        aggB = (nblk * 54) / 100;          // ~54% producers
        if (aggB < 1) aggB = 1;
        if (nblk - aggB < 1) aggB = nblk - 1;
    }

    k_degcnt<<<(EE + 255) / 256, 256>>>(ei, ew);                      // 1
    k_scan_prep<<<1, 1024>>>(att, Wz, bz, lzw, lzb, Wr, br, lrw, lrb,
                             Wh, bh, lhw, lhb);                       // 2
    k_fill<<<(EE + 255) / 256, 256>>>(ei, ew);                        // 3
    k_fused<<<nblk, 128>>>(x, linw, linb, out, aggB, nblk);           // 4

    (void)n_in; (void)out_size;
}

// round 11
// speedup vs baseline: 1.9427x; 1.9427x over previous
#include <cuda_runtime.h>
#include <cuda_bf16.h>
#include <cstdint>

// Problem constants (fixed-shape problem)
#define BB 4
#define TT 12
#define NN 10000
#define FF 32
#define EE 160000
#define MM (BB*NN)          // 40000 rows
#define SLICES (BB*TT)      // 48
#define SL (NN*FF)          // 320000 elements per slice
#define SL2 (SL/2)          // slice stride in float2/ull units

typedef unsigned long long ull;

// -------- device scratch (static, no allocation; zero-initialized) --------
__device__ float d_XA[SLICES * NN * FF];   // aggregated features (61.4MB)
__device__ float d_deg[NN];
__device__ float d_dinv[NN];
__device__ int   d_cnt[NN];
__device__ int   d_fill[NN];
__device__ int   d_rowptr[NN + 1];
__device__ int2  d_csrp[EE];               // packed {src_row, weight_bits}
__device__ float d_bf[96];                 // folded biases z|r|h
__device__ float d_probs[TT];
// mma fragment-ordered bf16x2 weights: [term(hi/lo)][nt][kt][lane][reg]
__device__ uint32_t d_fB1[2 * 12 * 4 * 32 * 2];   // gates B: K=64, N=96
__device__ uint32_t d_fUh[2 * 4 * 2 * 32 * 2];    // Uh:      K=32, N=32
__device__ uint32_t d_fLn[2 * 4 * 2 * 32 * 2];    // lin_w:   K=32, N=32

// ===================== f32x2 helpers (k_agg) =====================
__device__ __forceinline__ void fma2(ull& d, ull a, ull b) {
    asm("fma.rn.f32x2 %0, %1, %2, %0;" : "+l"(d) : "l"(a), "l"(b));
}
__device__ __forceinline__ void mul2(ull& d, ull a, ull b) {
    asm("mul.rn.f32x2 %0, %1, %2;" : "=l"(d) : "l"(a), "l"(b));
}
__device__ __forceinline__ ull splat2(float w) {
    ull r; asm("mov.b64 %0, {%1, %1};" : "=l"(r) : "f"(w)); return r;
}
__device__ __forceinline__ float2 unpk(ull a) {
    float2 f; asm("mov.b64 {%0, %1}, %2;" : "=f"(f.x), "=f"(f.y) : "l"(a)); return f;
}

// ===================== bf16 split/pack helpers =====================
// pack (a low half, b high half) rounded to bf16
__device__ __forceinline__ uint32_t packbf(float a, float b) {
    uint32_t r;
    asm("cvt.rn.bf16x2.f32 %0, %1, %2;" : "=r"(r) : "f"(b), "f"(a));
    return r;
}
// 2-term split of a pair: hi = rn(v), lo = rn(v - hi)
__device__ __forceinline__ void split2(float a, float b, uint32_t& hi, uint32_t& lo) {
    hi = packbf(a, b);
    float ha = __uint_as_float(hi << 16);
    float hb = __uint_as_float(hi & 0xffff0000u);
    lo = packbf(a - ha, b - hb);
}

// mma.sync m16n8k16 row.col bf16 -> f32, D += A*B
__device__ __forceinline__ void mma16816(float* d, const uint32_t* a,
                                         uint32_t b0, uint32_t b1) {
    asm("mma.sync.aligned.m16n8k16.row.col.f32.bf16.bf16.f32 "
        "{%0,%1,%2,%3}, {%4,%5,%6,%7}, {%8,%9}, {%0,%1,%2,%3};"
        : "+f"(d[0]), "+f"(d[1]), "+f"(d[2]), "+f"(d[3])
        : "r"(a[0]), "r"(a[1]), "r"(a[2]), "r"(a[3]), "r"(b0), "r"(b1));
}

// -------- degree/count accumulation --------
__global__ void k_degcnt(const int* ei, const float* ew) {
    int e = blockIdx.x * blockDim.x + threadIdx.x;
    if (e >= EE) return;
    int col = ei[EE + e];
    atomicAdd(&d_deg[col], ew[e]);
    atomicAdd(&d_cnt[col], 1);
}

// B1 element (k in [0,64), j in [0,96)): [W'z|W'r|W'h ; Uz|Ur|0]
__device__ __forceinline__ float b1elem(int k, int j,
        const float* Wz, const float* lzw, const float* Wr, const float* lrw,
        const float* Wh, const float* lhw) {
    int g = j >> 5, jj = j & 31;
    if (k < 32) {
        const float* Wg = (g == 0) ? Wz : (g == 1) ? Wr : Wh;
        const float* Lg = (g == 0) ? lzw : (g == 1) ? lrw : lhw;
        float s = 0.f;
        #pragma unroll
        for (int m = 0; m < 32; m++) s += Wg[k * 32 + m] * Lg[m * 32 + jj];
        return s;
    }
    return (g == 0) ? lzw[k * 32 + jj] : (g == 1) ? lrw[k * 32 + jj] : 0.f;
}

// single-block: dinv + scan + bias fold + softmax + fragment build + re-zero
__global__ void k_scan_prep(const float* att,
                            const float* Wz, const float* bz, const float* lzw, const float* lzb,
                            const float* Wr, const float* br, const float* lrw, const float* lrb,
                            const float* Wh, const float* bh, const float* lhw, const float* lhb,
                            const float* linw) {
    int tid = threadIdx.x;
    int lane = tid & 31;

    // ---- B1 fragments (hi/lo), fragment-native ordering ----
    for (int i = tid; i < 12 * 4 * 32; i += 1024) {
        int nt = i >> 7;
        int kt = (i >> 5) & 3;
        int ln = i & 31;
        int n = nt * 8 + (ln >> 2);
        int kb = kt * 16 + (ln & 3) * 2;
        #pragma unroll
        for (int r = 0; r < 2; r++) {
            int k0 = kb + r * 8;
            float w0 = b1elem(k0, n, Wz, lzw, Wr, lrw, Wh, lhw);
            float w1 = b1elem(k0 + 1, n, Wz, lzw, Wr, lrw, Wh, lhw);
            uint32_t hi, lo;
            split2(w0, w1, hi, lo);
            d_fB1[((0 * 12 + nt) * 4 + kt) * 64 + ln * 2 + r] = hi;
            d_fB1[((1 * 12 + nt) * 4 + kt) * 64 + ln * 2 + r] = lo;
        }
    }
    // ---- Uh + Ln fragments (K=32 -> kt in {0,1}, N=32 -> nt in {0..3}) ----
    for (int i = tid; i < 4 * 2 * 32; i += 1024) {
        int nt = i >> 6;
        int kt = (i >> 5) & 1;
        int ln = i & 31;
        int n = nt * 8 + (ln >> 2);
        int kb = kt * 16 + (ln & 3) * 2;
        #pragma unroll
        for (int r = 0; r < 2; r++) {
            int k0 = kb + r * 8;
            float u0 = lhw[(32 + k0) * 32 + n];
            float u1 = lhw[(32 + k0 + 1) * 32 + n];
            float l0 = linw[k0 * 32 + n];
            float l1 = linw[(k0 + 1) * 32 + n];
            uint32_t hi, lo;
            split2(u0, u1, hi, lo);
            d_fUh[((0 * 4 + nt) * 2 + kt) * 64 + ln * 2 + r] = hi;
            d_fUh[((1 * 4 + nt) * 2 + kt) * 64 + ln * 2 + r] = lo;
            split2(l0, l1, hi, lo);
            d_fLn[((0 * 4 + nt) * 2 + kt) * 64 + ln * 2 + r] = hi;
            d_fLn[((1 * 4 + nt) * 2 + kt) * 64 + ln * 2 + r] = lo;
        }
    }
    // ---- folded biases + softmax ----
    if (tid < 96) {
        int g = tid >> 5; int jj = tid & 31;
        const float* bs = (g == 0) ? bz : (g == 1) ? br : bh;
        const float* ls = (g == 0) ? lzw : (g == 1) ? lrw : lhw;
        const float* lb = (g == 0) ? lzb : (g == 1) ? lrb : lhb;
        float s = lb[jj];
        for (int m = 0; m < 32; m++) s += bs[m] * ls[m * 32 + jj];
        d_bf[g * 32 + jj] = s;
    }
    if (tid == 0) {
        float mx = -1e30f;
        for (int i = 0; i < TT; i++) mx = fmaxf(mx, att[i]);
        float e[TT]; float sum = 0.f;
        for (int i = 0; i < TT; i++) { e[i] = expf(att[i] - mx); sum += e[i]; }
        for (int i = 0; i < TT; i++) d_probs[i] = e[i] / sum;
    }

    // ---- dinv ----
    for (int i = tid; i < NN; i += 1024) {
        float d = d_deg[i] + 1.0f;
        d_dinv[i] = rsqrtf(fmaxf(d, 1e-12f));
    }
    // ---- 3-level exclusive scan ----
    __shared__ int warpsum[32];
    int v[10];
    int s = 0;
    int base = tid * 10;
    if (tid < 1000) {
        #pragma unroll
        for (int u = 0; u < 10; u++) { v[u] = s; s += d_cnt[base + u]; }
    }
    int inc = s;
    #pragma unroll
    for (int o = 1; o < 32; o <<= 1) {
        int t = __shfl_up_sync(0xffffffffu, inc, o);
        if (lane >= o) inc += t;
    }
    if (lane == 31) warpsum[tid >> 5] = inc;
    __syncthreads();
    if (tid < 32) {
        int ws = warpsum[tid];
        int winc = ws;
        #pragma unroll
        for (int o = 1; o < 32; o <<= 1) {
            int t = __shfl_up_sync(0xffffffffu, winc, o);
            if (lane >= o) winc += t;
        }
        warpsum[tid] = winc - ws;
    }
    __syncthreads();
    int texcl = warpsum[tid >> 5] + inc - s;
    if (tid < 1000) {
        #pragma unroll
        for (int u = 0; u < 10; u++) d_rowptr[base + u] = texcl + v[u];
    }
    if (tid == 1000) d_rowptr[NN] = texcl;

    __syncthreads();
    for (int i = tid; i < NN; i += 1024) { d_deg[i] = 0.f; d_cnt[i] = 0; d_fill[i] = 0; }
}

__global__ void k_fill(const int* ei, const float* ew) {
    int e = blockIdx.x * blockDim.x + threadIdx.x;
    if (e >= EE) return;
    int r = ei[e];
    int c = ei[EE + e];
    int pos = d_rowptr[c] + atomicAdd(&d_fill[c], 1);
    float w = d_dinv[r] * ew[e] * d_dinv[c];
    d_csrp[pos] = make_int2(r, __float_as_int(w));
}

// -------- aggregation (unchanged from 294.9 baseline) --------
__global__ void __launch_bounds__(256) k_agg(const float* __restrict__ x) {
    int w = (blockIdx.x * blockDim.x + threadIdx.x) >> 5;
    int lane = threadIdx.x & 31;
    if (w >= NN * 6) return;
    int g = w / NN;
    int n = w - g * NN;
    int half = lane >> 4;
    int fp = lane & 15;

    const ull* px = (const ull*)x;
    int sbase = g * 8 + half;
    long ofs0 = (long)(sbase + 0) * SL2 + fp;
    long ofs1 = (long)(sbase + 2) * SL2 + fp;
    long ofs2 = (long)(sbase + 4) * SL2 + fp;
    long ofs3 = (long)(sbase + 6) * SL2 + fp;

    float dn = d_dinv[n];
    ull selfw2 = splat2(dn * dn);
    ull acc0, acc1, acc2, acc3;
    {
        int r16 = n * 16;
        mul2(acc0, __ldg(px + ofs0 + r16), selfw2);
        mul2(acc1, __ldg(px + ofs1 + r16), selfw2);
        mul2(acc2, __ldg(px + ofs2 + r16), selfw2);
        mul2(acc3, __ldg(px + ofs3 + r16), selfw2);
    }
    int e0 = d_rowptr[n], e1 = d_rowptr[n + 1];
    int2 ed;
    if (e0 < e1) ed = __ldg(&d_csrp[e0]);
    for (int e = e0; e < e1; e++) {
        int2 edn;
        if (e + 1 < e1) edn = __ldg(&d_csrp[e + 1]);
        ull w2 = splat2(__int_as_float(ed.y));
        int r16 = ed.x * 16;
        ull v0 = __ldg(px + ofs0 + r16);
        ull v1 = __ldg(px + ofs1 + r16);
        ull v2 = __ldg(px + ofs2 + r16);
        ull v3 = __ldg(px + ofs3 + r16);
        fma2(acc0, v0, w2);
        fma2(acc1, v1, w2);
        fma2(acc2, v2, w2);
        fma2(acc3, v3, w2);
        ed = edn;
    }
    float2* po = (float2*)d_XA;
    int n16 = n * 16 + fp;
    __stcs(po + (long)(sbase + 0) * SL2 + n16, unpk(acc0));
    __stcs(po + (long)(sbase + 2) * SL2 + n16, unpk(acc1));
    __stcs(po + (long)(sbase + 4) * SL2 + n16, unpk(acc2));
    __stcs(po + (long)(sbase + 6) * SL2 + n16, unpk(acc3));
}

// ==================== warp-MMA GRU ====================
// Warp owns 16 rows; h/hacc live in D-fragment registers for all 12 steps.
// Gate GEMM per step: D[16,96] = [xa|h][16,64] @ B1[64,96] (+bias), with
// ah columns (64-95) extended by hr[16,32] @ Uh[32,32]. All mmas are
// 3-term bf16 splits: hi*hi + hi*lo + lo*hi.
__global__ void __launch_bounds__(128)
k_gruw(const float* __restrict__ linb, float* __restrict__ out) {
    __shared__ uint32_t sB1[6144];        // 24KB
    __shared__ uint32_t sUh[1024];        // 4KB
    __shared__ uint32_t sLn[1024];        // 4KB
    __shared__ float sbias[96];
    __shared__ float sprob[16];

    int tid = threadIdx.x;
    for (int i = tid; i < 6144; i += 128) sB1[i] = d_fB1[i];
    for (int i = tid; i < 1024; i += 128) { sUh[i] = d_fUh[i]; sLn[i] = d_fLn[i]; }
    if (tid < 96) sbias[tid] = d_bf[tid];
    if (tid < TT) sprob[tid] = d_probs[tid];
    __syncthreads();

    int lane = tid & 31;
    int wid = tid >> 5;
    int m0 = (blockIdx.x * 4 + wid) * 16;      // NN%16==0 -> no batch straddle
    int b = m0 / NN;
    long base = (long)b * (TT * SL) + (long)(m0 - b * NN) * 32;
    int r1 = lane >> 2;                        // fragment row (0..7)
    int c0 = (lane & 3) * 2;                   // fragment col base
    const float* xr1 = d_XA + base + (long)r1 * 32 + c0;        // row r1
    const float* xr2 = xr1 + 8 * 32;                            // row r1+8

    // h, hacc in D-fragment layout: [nt(0..3)][i(0..3)]
    float h[16], hacc[16];
    #pragma unroll
    for (int j = 0; j < 16; j++) { h[j] = 0.f; hacc[j] = 0.f; }

    for (int t = 0; t < TT; t++) {
        // ---- load xa (rows r1, r1+8; 4 col-pairs each) ----
        float2 x1[4], x2[4];
        #pragma unroll
        for (int q = 0; q < 4; q++) {
            x1[q] = __ldg((const float2*)(xr1 + (long)t * SL + 8 * q));
            x2[q] = __ldg((const float2*)(xr2 + (long)t * SL + 8 * q));
        }
        // ---- A fragments: kt 0,1 from xa; kt 2,3 from h ----
        uint32_t ahi[4][4], alo[4][4];
        #pragma unroll
        for (int kt = 0; kt < 2; kt++) {
            split2(x1[2 * kt].x,     x1[2 * kt].y,     ahi[kt][0], alo[kt][0]);
            split2(x2[2 * kt].x,     x2[2 * kt].y,     ahi[kt][1], alo[kt][1]);
            split2(x1[2 * kt + 1].x, x1[2 * kt + 1].y, ahi[kt][2], alo[kt][2]);
            split2(x2[2 * kt + 1].x, x2[2 * kt + 1].y, ahi[kt][3], alo[kt][3]);
        }
        #pragma unroll
        for (int kt = 2; kt < 4; kt++) {
            int hn = 2 * (kt - 2);
            split2(h[hn * 4 + 0],       h[hn * 4 + 1],       ahi[kt][0], alo[kt][0]);
            split2(h[hn * 4 + 2],       h[hn * 4 + 3],       ahi[kt][1], alo[kt][1]);
            split2(h[(hn + 1) * 4 + 0], h[(hn + 1) * 4 + 1], ahi[kt][2], alo[kt][2]);
            split2(h[(hn + 1) * 4 + 2], h[(hn + 1) * 4 + 3], ahi[kt][3], alo[kt][3]);
        }

        // ---- z, r gates: N-tiles 0..7 ----
        float z[16], hr[16];
        #pragma unroll
        for (int nt = 0; nt < 8; nt++) {
            float d[4];
            #pragma unroll
            for (int i = 0; i < 4; i++) d[i] = sbias[8 * nt + c0 + (i & 1)];
            #pragma unroll
            for (int kt = 0; kt < 4; kt++) {
                const uint32_t* ph = &sB1[((0 * 12 + nt) * 4 + kt) * 64 + lane * 2];
                const uint32_t* pl = &sB1[((1 * 12 + nt) * 4 + kt) * 64 + lane * 2];
                uint2 bh = *(const uint2*)ph;
                uint2 bl = *(const uint2*)pl;
                mma16816(d, ahi[kt], bh.x, bh.y);
                mma16816(d, ahi[kt], bl.x, bl.y);
                mma16816(d, alo[kt], bh.x, bh.y);
            }
            if (nt < 4) {
                #pragma unroll
                for (int i = 0; i < 4; i++)
                    z[nt * 4 + i] = 1.f / (1.f + __expf(-d[i]));
            } else {
                int hn = nt - 4;
                #pragma unroll
                for (int i = 0; i < 4; i++) {
                    float rg = 1.f / (1.f + __expf(-d[i]));
                    hr[hn * 4 + i] = h[hn * 4 + i] * rg;
                }
            }
        }
        // ---- hr fragments (K=32 -> kt2 0,1) ----
        uint32_t rhi[2][4], rlo[2][4];
        #pragma unroll
        for (int kt = 0; kt < 2; kt++) {
            int hn = 2 * kt;
            split2(hr[hn * 4 + 0],       hr[hn * 4 + 1],       rhi[kt][0], rlo[kt][0]);
            split2(hr[hn * 4 + 2],       hr[hn * 4 + 3],       rhi[kt][1], rlo[kt][1]);
            split2(hr[(hn + 1) * 4 + 0], hr[(hn + 1) * 4 + 1], rhi[kt][2], rlo[kt][2]);
            split2(hr[(hn + 1) * 4 + 2], hr[(hn + 1) * 4 + 3], rhi[kt][3], rlo[kt][3]);
        }

        // ---- ah tiles: N-tiles 8..11, K = [xa|h] + hr@Uh ----
        float pt = sprob[t];
        #pragma unroll
        for (int nt = 8; nt < 12; nt++) {
            float d[4];
            #pragma unroll
            for (int i = 0; i < 4; i++) d[i] = sbias[8 * nt + c0 + (i & 1)];
            #pragma unroll
            for (int kt = 0; kt < 4; kt++) {
                const uint32_t* ph = &sB1[((0 * 12 + nt) * 4 + kt) * 64 + lane * 2];
                const uint32_t* pl = &sB1[((1 * 12 + nt) * 4 + kt) * 64 + lane * 2];
                uint2 bh = *(const uint2*)ph;
                uint2 bl = *(const uint2*)pl;
                mma16816(d, ahi[kt], bh.x, bh.y);
                mma16816(d, ahi[kt], bl.x, bl.y);
                mma16816(d, alo[kt], bh.x, bh.y);
            }
            int un = nt - 8;
            #pragma unroll
            for (int kt = 0; kt < 2; kt++) {
                const uint32_t* ph = &sUh[((0 * 4 + un) * 2 + kt) * 64 + lane * 2];
                const uint32_t* pl = &sUh[((1 * 4 + un) * 2 + kt) * 64 + lane * 2];
                uint2 bh = *(const uint2*)ph;
                uint2 bl = *(const uint2*)pl;
                mma16816(d, rhi[kt], bh.x, bh.y);
                mma16816(d, rhi[kt], bl.x, bl.y);
                mma16816(d, rlo[kt], bh.x, bh.y);
            }
            #pragma unroll
            for (int i = 0; i < 4; i++) {
                int j = un * 4 + i;
                float ht = 2.f / (1.f + __expf(-2.f * d[i])) - 1.f;   // tanh
                h[j] = z[j] * h[j] + (1.f - z[j]) * ht;
                hacc[j] += pt * h[j];
            }
        }
    }

    // ---- final: out = relu(hacc) @ lin_w + lin_b ----
    uint32_t rhi[2][4], rlo[2][4];
    #pragma unroll
    for (int kt = 0; kt < 2; kt++) {
        int hn = 2 * kt;
        split2(fmaxf(hacc[hn * 4 + 0], 0.f),       fmaxf(hacc[hn * 4 + 1], 0.f),       rhi[kt][0], rlo[kt][0]);
        split2(fmaxf(hacc[hn * 4 + 2], 0.f),       fmaxf(hacc[hn * 4 + 3], 0.f),       rhi[kt][1], rlo[kt][1]);
        split2(fmaxf(hacc[(hn + 1) * 4 + 0], 0.f), fmaxf(hacc[(hn + 1) * 4 + 1], 0.f), rhi[kt][2], rlo[kt][2]);
        split2(fmaxf(hacc[(hn + 1) * 4 + 2], 0.f), fmaxf(hacc[(hn + 1) * 4 + 3], 0.f), rhi[kt][3], rlo[kt][3]);
    }
    #pragma unroll
    for (int nt = 0; nt < 4; nt++) {
        float d[4];
        float lb0 = __ldg(&linb[8 * nt + c0]);
        float lb1 = __ldg(&linb[8 * nt + c0 + 1]);
        d[0] = lb0; d[1] = lb1; d[2] = lb0; d[3] = lb1;
        #pragma unroll
        for (int kt = 0; kt < 2; kt++) {
            const uint32_t* ph = &sLn[((0 * 4 + nt) * 2 + kt) * 64 + lane * 2];
            const uint32_t* pl = &sLn[((1 * 4 + nt) * 2 + kt) * 64 + lane * 2];
            uint2 bh = *(const uint2*)ph;
            uint2 bl = *(const uint2*)pl;
            mma16816(d, rhi[kt], bh.x, bh.y);
            mma16816(d, rhi[kt], bl.x, bl.y);
            mma16816(d, rlo[kt], bh.x, bh.y);
        }
        // store: row r1 cols (8nt+c0, +1); row r1+8 same cols
        *(float2*)(out + (long)(m0 + r1) * 32 + 8 * nt + c0)     = make_float2(d[0], d[1]);
        *(float2*)(out + (long)(m0 + r1 + 8) * 32 + 8 * nt + c0) = make_float2(d[2], d[3]);
    }
}

extern "C" void kernel_launch(void* const* d_in, const int* in_sizes, int n_in,
                              void* d_out, int out_size) {
    const float* x  = (const float*)d_in[0];
    const int*   ei = (const int*)d_in[1];
    const float* ew = (const float*)d_in[2];

    int iWz, iBz, iLzw, iLzb, iWr, iBr, iLrw, iLrb, iWh, iBh, iLhw, iLhb;
    if (in_sizes[5] == 2048) {
        iWz = 3; iBz = 4; iLzw = 5;  iLzb = 6;
        iWr = 7; iBr = 8; iLrw = 9;  iLrb = 10;
        iWh = 11; iBh = 12; iLhw = 13; iLhb = 14;
    } else {
        iWz = 3; iBz = 4; iWr = 5; iBr = 6; iWh = 7; iBh = 8;
        iLzw = 9; iLzb = 10; iLrw = 11; iLrb = 12; iLhw = 13; iLhb = 14;
    }
    const float* Wz  = (const float*)d_in[iWz];
    const float* bz  = (const float*)d_in[iBz];
    const float* lzw = (const float*)d_in[iLzw];
    const float* lzb = (const float*)d_in[iLzb];
    const float* Wr  = (const float*)d_in[iWr];
    const float* br  = (const float*)d_in[iBr];
    const float* lrw = (const float*)d_in[iLrw];
    const float* lrb = (const float*)d_in[iLrb];
    const float* Wh  = (const float*)d_in[iWh];
    const float* bh  = (const float*)d_in[iBh];
    const float* lhw = (const float*)d_in[iLhw];
    const float* lhb = (const float*)d_in[iLhb];
    const float* att  = (const float*)d_in[15];
    const float* linw = (const float*)d_in[16];
    const float* linb = (const float*)d_in[17];
    float* out = (float*)d_out;

    k_degcnt<<<(EE + 255) / 256, 256>>>(ei, ew);                      // 1
    k_scan_prep<<<1, 1024>>>(att, Wz, bz, lzw, lzb, Wr, br, lrw, lrb,
                             Wh, bh, lhw, lhb, linw);                 // 2
    k_fill<<<(EE + 255) / 256, 256>>>(ei, ew);                        // 3
    {   // 4: aggregation (ncu captures this one)
        int threads = NN * 6 * 32;
        k_agg<<<(threads + 255) / 256, 256>>>(x);
    }
    k_gruw<<<MM / 64, 128>>>(linb, out);                              // 5

    (void)n_in; (void)out_size;
}